// round 8
// baseline (speedup 1.0000x reference)
#include <cuda_runtime.h>
#include <cuda_bf16.h>

#define TILE 256
#define MAX_TILES 512
#define MAX_PER_TILE 4096

#define TWO_PI_F   6.2831855f      /* float32(2*pi) — matches jnp two_pi */
#define INV_2PI_F  0.15915494f
#define CW_HI      6.28125f        /* 7 mantissa bits: k*CW_HI exact for k<2^12 */
#define CW_MID     1.9353072e-3f   /* float(2*pi - 6.28125) */

// XLA-GPU lowers f32 divide to div.full.f32 (fast full-range, <=2ulp, NOT
// correctly rounded). Emulate it exactly — this is the reference's t grid.
__device__ __forceinline__ float div_full(float a, float b) {
    float r;
    asm("div.full.f32 %0, %1, %2;" : "=f"(r) : "f"(a), "f"(b));
    return r;
}

// Scratch (static __device__ arrays — allocation-free per harness rules)
__device__ int    g_tile_count[MAX_TILES];
__device__ float4 g_packA[(size_t)MAX_TILES * MAX_PER_TILE]; // {a, tau, omega, 4*sigma}
__device__ float4 g_packB[(size_t)MAX_TILES * MAX_PER_TILE]; // {phi, 0.5*gamma, denom, 0}

// ---------------------------------------------------------------------------
// Binning: one block per time tile; deterministic ordered compaction (atom
// index order preserved) of atoms whose window [tau-4s, tau+4s] intersects
// the tile span. 1e-4 s slack >> any 2-ulp t-grid discrepancy.
// ---------------------------------------------------------------------------
__global__ void bin_kernel(const float* __restrict__ amp,
                           const float* __restrict__ tau,
                           const float* __restrict__ om,
                           const float* __restrict__ sg,
                           const float* __restrict__ ph,
                           const float* __restrict__ gm,
                           int N, int num_tiles, int T)
{
    int tile = blockIdx.x;
    if (tile >= num_tiles) return;

    int s0 = tile * TILE;
    int s1 = min(s0 + TILE - 1, T - 1);
    float t_lo = (float)s0 / 24000.0f - 1e-4f;
    float t_hi = (float)s1 / 24000.0f + 1e-4f;

    __shared__ int s_base;
    __shared__ int s_warp_cnt[8];
    if (threadIdx.x == 0) s_base = 0;
    __syncthreads();

    int lane = threadIdx.x & 31;
    int wid  = threadIdx.x >> 5;
    int nwarps = (int)(blockDim.x >> 5);

    for (int base = 0; base < N; base += blockDim.x) {
        int i = base + (int)threadIdx.x;
        bool act = false;
        float a = 0.f, tu = 0.f, o = 0.f, s = 0.f, p = 0.f, g = 0.f;
        if (i < N) {
            tu = tau[i];
            s  = sg[i];
            float halfw = 4.0f * s;   // exact
            act = (tu - halfw <= t_hi) && (tu + halfw >= t_lo);
            if (act) { a = amp[i]; o = om[i]; p = ph[i]; g = gm[i]; }
        }
        unsigned m = __ballot_sync(0xFFFFFFFFu, act);
        if (lane == 0) s_warp_cnt[wid] = __popc(m);
        __syncthreads();

        int woff = 0;
        for (int w = 0; w < wid; w++) woff += s_warp_cnt[w];
        int total = 0;
        for (int w = 0; w < nwarps; w++) total += s_warp_cnt[w];

        if (act) {
            int idx = s_base + woff + __popc(m & ((1u << lane) - 1u));
            if (idx < MAX_PER_TILE) {
                size_t off = (size_t)tile * MAX_PER_TILE + (size_t)idx;
                g_packA[off] = make_float4(a, tu, o, __fmul_rn(4.0f, s));
                // denom = 2.0*sg**2 + 1e-8 with reference rounding
                float denom = __fadd_rn(__fmul_rn(2.0f, __fmul_rn(s, s)), 1e-8f);
                g_packB[off] = make_float4(p, __fmul_rn(0.5f, g), denom, 0.0f);
            }
        }
        __syncthreads();
        if (threadIdx.x == 0) s_base += total;
        __syncthreads();
    }
    if (threadIdx.x == 0) g_tile_count[tile] = min(s_base, MAX_PER_TILE);
}

// ---------------------------------------------------------------------------
// Render: one block per tile, one thread per sample.
//   t via div.full.f32 (XLA-GPU's divide lowering — the reference's grid),
//   bit-exact non-contracted f32 phase chain,
//   exact Cody-Waite mod-2pi + __cosf, __expf for the envelope.
// ---------------------------------------------------------------------------
__global__ void __launch_bounds__(TILE) render_kernel(float* __restrict__ out, int T)
{
    int tile = blockIdx.x;
    int s = tile * TILE + (int)threadIdx.x;
    float t = div_full((float)s, 24000.0f);   // matches XLA-GPU arange/SR

    int cnt = g_tile_count[tile];
    const float4* __restrict__ pA = g_packA + (size_t)tile * MAX_PER_TILE;
    const float4* __restrict__ pB = g_packB + (size_t)tile * MAX_PER_TILE;

    float acc = 0.0f;
    for (int j = 0; j < cnt; j++) {
        float4 A = __ldg(pA + j);   // a, tau, omega, 4sigma
        float4 B = __ldg(pB + j);   // phi, 0.5*gamma, denom, -

        float tc = __fadd_rn(t, -A.y);          // t - tau, reference rounding

        // env argument like reference: ((-tc)*tc)/denom via div.full
        float num = __fmul_rn(-tc, tc);
        float arg = div_full(num, B.z);
        float env = __expf(arg);

        // phase, bitwise like reference (left-assoc, no contraction):
        //   two_pi*(om*tc + ((0.5*gm)*tc)*tc) + phi
        float r1  = __fmul_rn(A.z, tc);
        float r3  = __fmul_rn(B.y, tc);
        float r4  = __fmul_rn(r3, tc);
        float sm  = __fadd_rn(r1, r4);
        float p2  = __fmul_rn(TWO_PI_F, sm);
        float phase = __fadd_rn(p2, B.x);

        // Exact Cody-Waite mod 2pi (k < 2^12 so k*CW_HI exact), then MUFU cos.
        float k    = rintf(__fmul_rn(phase, INV_2PI_F));
        float red  = fmaf(-k, CW_HI, phase);
        red        = fmaf(-k, CW_MID, red);
        float c    = __cosf(red);

        float v = (fabsf(tc) <= A.w) ? (__fmul_rn(__fmul_rn(A.x, env), c)) : 0.0f;
        acc = __fadd_rn(acc, v);
    }
    if (s < T) out[s] = acc;
}

extern "C" void kernel_launch(void* const* d_in, const int* in_sizes, int n_in,
                              void* d_out, int out_size)
{
    const float* amp = (const float*)d_in[0];
    const float* tau = (const float*)d_in[1];
    const float* om  = (const float*)d_in[2];
    const float* sg  = (const float*)d_in[3];
    const float* ph  = (const float*)d_in[4];
    const float* gm  = (const float*)d_in[5];
    // d_in[6] = num_samples scalar — T comes from out_size.

    int N = in_sizes[0];
    int T = out_size;
    int num_tiles = (T + TILE - 1) / TILE;
    if (num_tiles > MAX_TILES) num_tiles = MAX_TILES;   // T=72000 -> 282 tiles

    bin_kernel<<<num_tiles, 256>>>(amp, tau, om, sg, ph, gm, N, num_tiles, T);
    render_kernel<<<num_tiles, TILE>>>((float*)d_out, T);
}

// round 9
// speedup vs baseline: 1.3146x; 1.3146x over previous
#include <cuda_runtime.h>
#include <cuda_bf16.h>

#define RTILE 128            /* samples per render block */
#define NSLICE 4             /* atom slices per sample  */
#define BIN 512              /* samples per bin list    */
#define MAX_BINS 256
#define MAX_PER_BIN 4096

#define TWO_PI_F   6.2831855f      /* float32(2*pi) — matches jnp two_pi */
#define INV_2PI_F  0.15915494f
#define CW_HI      6.28125f        /* 7 mantissa bits: k*CW_HI exact for k<2^12 */
#define CW_MID     1.9353072e-3f   /* float(2*pi - 6.28125) */

// XLA-GPU lowers f32 divide to div.full.f32 (<=2ulp, NOT correctly rounded).
// This is what makes the t grid match the reference.
__device__ __forceinline__ float div_full(float a, float b) {
    float r;
    asm("div.full.f32 %0, %1, %2;" : "=f"(r) : "f"(a), "f"(b));
    return r;
}

// Scratch (static __device__ arrays — allocation-free per harness rules)
__device__ int    g_bin_count[MAX_BINS];
__device__ float4 g_packA[(size_t)MAX_BINS * MAX_PER_BIN]; // {a, tau, omega, 4*sigma}
__device__ float4 g_packB[(size_t)MAX_BINS * MAX_PER_BIN]; // {phi, 0.5*gamma, -1/denom, 0}

// ---------------------------------------------------------------------------
// Binning at 512-sample granularity: deterministic ordered compaction of
// atoms whose window [tau-4s, tau+4s] intersects the bin span.
// ---------------------------------------------------------------------------
__global__ void bin_kernel(const float* __restrict__ amp,
                           const float* __restrict__ tau,
                           const float* __restrict__ om,
                           const float* __restrict__ sg,
                           const float* __restrict__ ph,
                           const float* __restrict__ gm,
                           int N, int num_bins, int T)
{
    int bin = blockIdx.x;
    if (bin >= num_bins) return;

    int s0 = bin * BIN;
    int s1 = min(s0 + BIN - 1, T - 1);
    float t_lo = (float)s0 / 24000.0f - 1e-4f;   // slack >> 2-ulp grid jitter
    float t_hi = (float)s1 / 24000.0f + 1e-4f;

    __shared__ int s_base;
    __shared__ int s_warp_cnt[8];
    if (threadIdx.x == 0) s_base = 0;
    __syncthreads();

    int lane = threadIdx.x & 31;
    int wid  = threadIdx.x >> 5;
    int nwarps = (int)(blockDim.x >> 5);

    for (int base = 0; base < N; base += blockDim.x) {
        int i = base + (int)threadIdx.x;
        bool act = false;
        float a = 0.f, tu = 0.f, o = 0.f, s = 0.f, p = 0.f, g = 0.f;
        if (i < N) {
            tu = tau[i];
            s  = sg[i];
            float halfw = 4.0f * s;   // exact
            act = (tu - halfw <= t_hi) && (tu + halfw >= t_lo);
            if (act) { a = amp[i]; o = om[i]; p = ph[i]; g = gm[i]; }
        }
        unsigned m = __ballot_sync(0xFFFFFFFFu, act);
        if (lane == 0) s_warp_cnt[wid] = __popc(m);
        __syncthreads();

        int woff = 0;
        for (int w = 0; w < wid; w++) woff += s_warp_cnt[w];
        int total = 0;
        for (int w = 0; w < nwarps; w++) total += s_warp_cnt[w];

        if (act) {
            int idx = s_base + woff + __popc(m & ((1u << lane) - 1u));
            if (idx < MAX_PER_BIN) {
                size_t off = (size_t)bin * MAX_PER_BIN + (size_t)idx;
                g_packA[off] = make_float4(a, tu, o, __fmul_rn(4.0f, s));
                // denom with reference rounding, then hoisted -1/denom (div.full)
                float denom = __fadd_rn(__fmul_rn(2.0f, __fmul_rn(s, s)), 1e-8f);
                float ninv  = -div_full(1.0f, denom);
                g_packB[off] = make_float4(p, __fmul_rn(0.5f, g), ninv, 0.0f);
            }
        }
        __syncthreads();
        if (threadIdx.x == 0) s_base += total;
        __syncthreads();
    }
    if (threadIdx.x == 0) g_bin_count[bin] = min(s_base, MAX_PER_BIN);
}

// ---------------------------------------------------------------------------
// Render: block = 128 samples x 4 atom-slices (512 threads). Each slice
// accumulates atoms j = slice, slice+4, ... from the parent bin's list
// (warp-uniform float4 loads), partials combined in smem in fixed order
// (deterministic). t grid via div.full (the reference-matching divide);
// bit-exact non-contracted phase chain; exact Cody-Waite + __cosf.
// ---------------------------------------------------------------------------
__global__ void __launch_bounds__(RTILE * NSLICE)
render_kernel(float* __restrict__ out, int T)
{
    __shared__ float s_part[NSLICE][RTILE];

    int tile  = blockIdx.x;
    int x     = threadIdx.x & (RTILE - 1);
    int slice = threadIdx.x >> 7;            // RTILE=128
    int s     = tile * RTILE + x;
    float t   = div_full((float)s, 24000.0f);

    int bin = (tile * RTILE) / BIN;
    int cnt = g_bin_count[bin];
    const float4* __restrict__ pA = g_packA + (size_t)bin * MAX_PER_BIN;
    const float4* __restrict__ pB = g_packB + (size_t)bin * MAX_PER_BIN;

    float acc = 0.0f;
    for (int j = slice; j < cnt; j += NSLICE) {
        float4 A = __ldg(pA + j);   // a, tau, omega, 4sigma
        float4 B = __ldg(pB + j);   // phi, 0.5*gamma, -1/denom, -

        float tc  = __fadd_rn(t, -A.y);        // t - tau, reference rounding
        float tc2 = __fmul_rn(tc, tc);
        float env = __expf(tc2 * B.z);         // arg within ~2ulp of ref's div.full

        // phase, bitwise like reference (left-assoc, no contraction):
        float r1  = __fmul_rn(A.z, tc);
        float r3  = __fmul_rn(B.y, tc);
        float r4  = __fmul_rn(r3, tc);
        float sm  = __fadd_rn(r1, r4);
        float p2  = __fmul_rn(TWO_PI_F, sm);
        float phase = __fadd_rn(p2, B.x);

        // Exact Cody-Waite mod 2pi, then MUFU cos.
        float k    = rintf(__fmul_rn(phase, INV_2PI_F));
        float red  = fmaf(-k, CW_HI, phase);
        red        = fmaf(-k, CW_MID, red);
        float c    = __cosf(red);

        float v = (fabsf(tc) <= A.w) ? (__fmul_rn(__fmul_rn(A.x, env), c)) : 0.0f;
        acc = __fadd_rn(acc, v);
    }

    s_part[slice][x] = acc;
    __syncthreads();

    if (slice == 0 && s < T) {
        float r = __fadd_rn(__fadd_rn(s_part[0][x], s_part[1][x]),
                            __fadd_rn(s_part[2][x], s_part[3][x]));
        out[s] = r;
    }
}

extern "C" void kernel_launch(void* const* d_in, const int* in_sizes, int n_in,
                              void* d_out, int out_size)
{
    const float* amp = (const float*)d_in[0];
    const float* tau = (const float*)d_in[1];
    const float* om  = (const float*)d_in[2];
    const float* sg  = (const float*)d_in[3];
    const float* ph  = (const float*)d_in[4];
    const float* gm  = (const float*)d_in[5];
    // d_in[6] = num_samples scalar — T comes from out_size.

    int N = in_sizes[0];
    int T = out_size;
    int num_bins  = (T + BIN - 1) / BIN;          // 72000 -> 141
    if (num_bins > MAX_BINS) num_bins = MAX_BINS;
    int num_tiles = (T + RTILE - 1) / RTILE;      // 72000 -> 563

    bin_kernel<<<num_bins, 256>>>(amp, tau, om, sg, ph, gm, N, num_bins, T);
    render_kernel<<<num_tiles, RTILE * NSLICE>>>((float*)d_out, T);
}

// round 11
// speedup vs baseline: 1.5523x; 1.1808x over previous
#include <cuda_runtime.h>
#include <cuda_bf16.h>

#define RTILE 128            /* samples per render block */
#define NSLICE 4             /* atom slices per sample  */
#define BIN 512              /* samples per bin list    */
#define MAX_BINS 256
#define MAX_PER_BIN 4096

#define TWO_PI_F   6.2831855f   /* float32(2*pi) — matches jnp two_pi */

// XLA-GPU lowers f32 divide to div.full.f32 (<=2ulp, NOT correctly rounded).
// This is what makes the t grid match the reference.
__device__ __forceinline__ float div_full(float a, float b) {
    float r;
    asm("div.full.f32 %0, %1, %2;" : "=f"(r) : "f"(a), "f"(b));
    return r;
}

// Scratch (static __device__ arrays — allocation-free per harness rules)
__device__ int    g_bin_count[MAX_BINS];
__device__ float4 g_packA[(size_t)MAX_BINS * MAX_PER_BIN]; // {tau, omega, 0.5*gamma, phi}
__device__ float4 g_packB[(size_t)MAX_BINS * MAX_PER_BIN]; // {a, -1/denom, 4*sigma, 0}

// ---------------------------------------------------------------------------
// Binning at 512-sample granularity (512 threads -> 8 sweeps): deterministic
// ordered compaction of atoms whose window intersects the bin span.
// Params stored UNSCALED (R9 numerics — the passing configuration).
// ---------------------------------------------------------------------------
__global__ void __launch_bounds__(512) bin_kernel(
    const float* __restrict__ amp,
    const float* __restrict__ tau,
    const float* __restrict__ om,
    const float* __restrict__ sg,
    const float* __restrict__ ph,
    const float* __restrict__ gm,
    int N, int num_bins, int T)
{
    int bin = blockIdx.x;
    if (bin >= num_bins) return;

    int s0 = bin * BIN;
    int s1 = min(s0 + BIN - 1, T - 1);
    float t_lo = (float)s0 / 24000.0f - 1e-4f;   // slack >> 2-ulp grid jitter
    float t_hi = (float)s1 / 24000.0f + 1e-4f;

    __shared__ int s_base;
    __shared__ int s_warp_cnt[16];
    if (threadIdx.x == 0) s_base = 0;
    __syncthreads();

    int lane = threadIdx.x & 31;
    int wid  = threadIdx.x >> 5;
    int nwarps = (int)(blockDim.x >> 5);

    for (int base = 0; base < N; base += blockDim.x) {
        int i = base + (int)threadIdx.x;
        bool act = false;
        float a = 0.f, tu = 0.f, o = 0.f, s = 0.f, p = 0.f, g = 0.f;
        if (i < N) {
            tu = tau[i];
            s  = sg[i];
            float halfw = 4.0f * s;   // exact
            act = (tu - halfw <= t_hi) && (tu + halfw >= t_lo);
            if (act) { a = amp[i]; o = om[i]; p = ph[i]; g = gm[i]; }
        }
        unsigned m = __ballot_sync(0xFFFFFFFFu, act);
        if (lane == 0) s_warp_cnt[wid] = __popc(m);
        __syncthreads();

        int woff = 0;
        for (int w = 0; w < wid; w++) woff += s_warp_cnt[w];
        int total = 0;
        for (int w = 0; w < nwarps; w++) total += s_warp_cnt[w];

        if (act) {
            int idx = s_base + woff + __popc(m & ((1u << lane) - 1u));
            if (idx < MAX_PER_BIN) {
                size_t off = (size_t)bin * MAX_PER_BIN + (size_t)idx;
                g_packA[off] = make_float4(tu, o, __fmul_rn(0.5f, g), p);
                float denom = __fadd_rn(__fmul_rn(2.0f, __fmul_rn(s, s)), 1e-8f);
                float ninv  = -div_full(1.0f, denom);    // R9's proven env form
                g_packB[off] = make_float4(a, ninv, __fmul_rn(4.0f, s), 0.0f);
            }
        }
        __syncthreads();
        if (threadIdx.x == 0) s_base += total;
        __syncthreads();
    }
    if (threadIdx.x == 0) g_bin_count[bin] = min(s_base, MAX_PER_BIN);
}

// ---------------------------------------------------------------------------
// Render: block = 128 samples x 4 atom-slices (512 threads).
// Numerics = R9's passing configuration (bit-exact non-contracted phase,
// __expf envelope) with ONE change: raw __cosf instead of Cody-Waite+__cosf
// (R1-vs-R3 quadrature bound raw-__cosf's contribution at <=3e-5).
// ---------------------------------------------------------------------------
__global__ void __launch_bounds__(RTILE * NSLICE)
render_kernel(float* __restrict__ out, int T)
{
    __shared__ float s_part[NSLICE][RTILE];

    int tile  = blockIdx.x;
    int x     = threadIdx.x & (RTILE - 1);
    int slice = threadIdx.x >> 7;            // RTILE=128
    int s     = tile * RTILE + x;
    float t   = div_full((float)s, 24000.0f);   // reference-matching t grid

    int bin = (tile * RTILE) / BIN;
    int cnt = g_bin_count[bin];
    const float4* __restrict__ pA = g_packA + (size_t)bin * MAX_PER_BIN;
    const float4* __restrict__ pB = g_packB + (size_t)bin * MAX_PER_BIN;

    float acc = 0.0f;
    #pragma unroll 4
    for (int j = slice; j < cnt; j += NSLICE) {
        float4 A = __ldg(pA + j);   // tau, omega, 0.5*gamma, phi
        float4 B = __ldg(pB + j);   // a, -1/denom, 4sigma, -

        float tc  = __fadd_rn(t, -A.x);        // t - tau, reference rounding
        float tc2 = __fmul_rn(tc, tc);
        float env = __expf(tc2 * B.y);         // R9's exact env form

        // phase, bitwise like reference (left-assoc, no contraction):
        //   two_pi*(om*tc + ((0.5*gm)*tc)*tc) + phi
        float r1  = __fmul_rn(A.y, tc);
        float r3  = __fmul_rn(A.z, tc);
        float r4  = __fmul_rn(r3, tc);
        float sm  = __fadd_rn(r1, r4);
        float p2  = __fmul_rn(TWO_PI_F, sm);
        float phase = __fadd_rn(p2, A.w);

        float c = __cosf(phase);               // raw MUFU path (R3-exonerated)

        float v = (fabsf(tc) <= B.z) ? (__fmul_rn(__fmul_rn(B.x, env), c)) : 0.0f;
        acc = __fadd_rn(acc, v);
    }

    s_part[slice][x] = acc;
    __syncthreads();

    if (slice == 0 && s < T) {
        float r = __fadd_rn(__fadd_rn(s_part[0][x], s_part[1][x]),
                            __fadd_rn(s_part[2][x], s_part[3][x]));
        out[s] = r;
    }
}

extern "C" void kernel_launch(void* const* d_in, const int* in_sizes, int n_in,
                              void* d_out, int out_size)
{
    const float* amp = (const float*)d_in[0];
    const float* tau = (const float*)d_in[1];
    const float* om  = (const float*)d_in[2];
    const float* sg  = (const float*)d_in[3];
    const float* ph  = (const float*)d_in[4];
    const float* gm  = (const float*)d_in[5];
    // d_in[6] = num_samples scalar — T comes from out_size.

    int N = in_sizes[0];
    int T = out_size;
    int num_bins  = (T + BIN - 1) / BIN;          // 72000 -> 141
    if (num_bins > MAX_BINS) num_bins = MAX_BINS;
    int num_tiles = (T + RTILE - 1) / RTILE;      // 72000 -> 563

    bin_kernel<<<num_bins, 512>>>(amp, tau, om, sg, ph, gm, N, num_bins, T);
    render_kernel<<<num_tiles, RTILE * NSLICE>>>((float*)d_out, T);
}

// round 12
// speedup vs baseline: 1.5940x; 1.0268x over previous
#include <cuda_runtime.h>
#include <cuda_bf16.h>

#define RTILE 256            /* samples per render block (2 per thread) */
#define NSLICE 4             /* atom slices per sample  */
#define BIN 512              /* samples per bin list    */
#define MAX_BINS 256
#define MAX_PER_BIN 4096

#define TWO_PI_F   6.2831855f   /* float32(2*pi) — matches jnp two_pi */
#define LOG2E_F    1.4426950408889634f

// XLA-GPU lowers f32 divide to div.full.f32 (<=2ulp, NOT correctly rounded).
// This is what makes the t grid match the reference.
__device__ __forceinline__ float div_full(float a, float b) {
    float r;
    asm("div.full.f32 %0, %1, %2;" : "=f"(r) : "f"(a), "f"(b));
    return r;
}
__device__ __forceinline__ float ex2(float x) {
    float r;
    asm("ex2.approx.f32 %0, %1;" : "=f"(r) : "f"(x));
    return r;
}

// Scratch (static __device__ arrays — allocation-free per harness rules)
__device__ int    g_bin_count[MAX_BINS];
__device__ float4 g_packA[(size_t)MAX_BINS * MAX_PER_BIN]; // {tau, omega, 0.5*gamma, phi}
__device__ float4 g_packB[(size_t)MAX_BINS * MAX_PER_BIN]; // {a, -log2e/denom, 4*sigma, 0}

// ---------------------------------------------------------------------------
// Binning at 512-sample granularity (512 threads -> 8 sweeps): deterministic
// ordered compaction of atoms whose window intersects the bin span.
// Phase params stored UNSCALED (the load-bearing numerics).
// ---------------------------------------------------------------------------
__global__ void __launch_bounds__(512) bin_kernel(
    const float* __restrict__ amp,
    const float* __restrict__ tau,
    const float* __restrict__ om,
    const float* __restrict__ sg,
    const float* __restrict__ ph,
    const float* __restrict__ gm,
    int N, int num_bins, int T)
{
    int bin = blockIdx.x;
    if (bin >= num_bins) return;

    int s0 = bin * BIN;
    int s1 = min(s0 + BIN - 1, T - 1);
    float t_lo = (float)s0 / 24000.0f - 1e-4f;   // slack >> 2-ulp grid jitter
    float t_hi = (float)s1 / 24000.0f + 1e-4f;

    __shared__ int s_base;
    __shared__ int s_warp_cnt[16];
    if (threadIdx.x == 0) s_base = 0;
    __syncthreads();

    int lane = threadIdx.x & 31;
    int wid  = threadIdx.x >> 5;
    int nwarps = (int)(blockDim.x >> 5);

    for (int base = 0; base < N; base += blockDim.x) {
        int i = base + (int)threadIdx.x;
        bool act = false;
        float a = 0.f, tu = 0.f, o = 0.f, s = 0.f, p = 0.f, g = 0.f;
        if (i < N) {
            tu = tau[i];
            s  = sg[i];
            float halfw = 4.0f * s;   // exact
            act = (tu - halfw <= t_hi) && (tu + halfw >= t_lo);
            if (act) { a = amp[i]; o = om[i]; p = ph[i]; g = gm[i]; }
        }
        unsigned m = __ballot_sync(0xFFFFFFFFu, act);
        if (lane == 0) s_warp_cnt[wid] = __popc(m);
        __syncthreads();

        int woff = 0;
        for (int w = 0; w < wid; w++) woff += s_warp_cnt[w];
        int total = 0;
        for (int w = 0; w < nwarps; w++) total += s_warp_cnt[w];

        if (act) {
            int idx = s_base + woff + __popc(m & ((1u << lane) - 1u));
            if (idx < MAX_PER_BIN) {
                size_t off = (size_t)bin * MAX_PER_BIN + (size_t)idx;
                g_packA[off] = make_float4(tu, o, __fmul_rn(0.5f, g), p);
                float denom = __fadd_rn(__fmul_rn(2.0f, __fmul_rn(s, s)), 1e-8f);
                // env coefficient with log2e folded: exp(-tc2/denom)=ex2(tc2*nk)
                float nk = -div_full(LOG2E_F, denom);   // env rel err ~3e-6: budgeted
                g_packB[off] = make_float4(a, nk, __fmul_rn(4.0f, s), 0.0f);
            }
        }
        __syncthreads();
        if (threadIdx.x == 0) s_base += total;
        __syncthreads();
    }
    if (threadIdx.x == 0) g_bin_count[bin] = min(s_base, MAX_PER_BIN);
}

// ---------------------------------------------------------------------------
// Render: block = 256 samples, 512 threads = 128 lanes x 4 atom-slices; each
// thread renders TWO samples (x and x+128) per atom load — halving LDG
// traffic and loop overhead per eval. Phase = bit-exact non-contracted chain
// (load-bearing); envelope = ex2-folded; cos = raw __cosf (both exonerated).
// Deterministic fixed-order smem combine.
// ---------------------------------------------------------------------------
__global__ void __launch_bounds__(512)
render_kernel(float* __restrict__ out, int T)
{
    __shared__ float s_part[NSLICE][RTILE];

    int tile  = blockIdx.x;
    int x     = threadIdx.x & 127;
    int slice = threadIdx.x >> 7;
    int sA    = tile * RTILE + x;          // sample 0
    int sB    = sA + 128;                  // sample 1
    float tA  = div_full((float)sA, 24000.0f);   // reference-matching t grid
    float tB  = div_full((float)sB, 24000.0f);

    int bin = (tile * RTILE) / BIN;        // = tile>>1
    int cnt = g_bin_count[bin];
    const float4* __restrict__ pA = g_packA + (size_t)bin * MAX_PER_BIN;
    const float4* __restrict__ pB = g_packB + (size_t)bin * MAX_PER_BIN;

    float accA = 0.0f, accB = 0.0f;
    #pragma unroll 2
    for (int j = slice; j < cnt; j += NSLICE) {
        float4 A = __ldg(pA + j);   // tau, omega, 0.5*gamma, phi
        float4 B = __ldg(pB + j);   // a, -log2e/denom, 4sigma, -

        // ---- sample A ----
        {
            float tc  = __fadd_rn(tA, -A.x);
            float tc2 = __fmul_rn(tc, tc);
            float env = ex2(tc2 * B.y);
            float r1  = __fmul_rn(A.y, tc);
            float r3  = __fmul_rn(A.z, tc);
            float r4  = __fmul_rn(r3, tc);
            float sm  = __fadd_rn(r1, r4);
            float p2  = __fmul_rn(TWO_PI_F, sm);
            float phase = __fadd_rn(p2, A.w);
            float c   = __cosf(phase);
            float v   = __fmul_rn(__fmul_rn(B.x, env), c);
            if (fabsf(tc) <= B.z) accA = __fadd_rn(accA, v);
        }
        // ---- sample B ----
        {
            float tc  = __fadd_rn(tB, -A.x);
            float tc2 = __fmul_rn(tc, tc);
            float env = ex2(tc2 * B.y);
            float r1  = __fmul_rn(A.y, tc);
            float r3  = __fmul_rn(A.z, tc);
            float r4  = __fmul_rn(r3, tc);
            float sm  = __fadd_rn(r1, r4);
            float p2  = __fmul_rn(TWO_PI_F, sm);
            float phase = __fadd_rn(p2, A.w);
            float c   = __cosf(phase);
            float v   = __fmul_rn(__fmul_rn(B.x, env), c);
            if (fabsf(tc) <= B.z) accB = __fadd_rn(accB, v);
        }
    }

    s_part[slice][x] = accA;
    __syncthreads();
    if (slice == 0 && sA < T) {
        float r = __fadd_rn(__fadd_rn(s_part[0][x], s_part[1][x]),
                            __fadd_rn(s_part[2][x], s_part[3][x]));
        out[sA] = r;
    }
    __syncthreads();
    s_part[slice][x] = accB;
    __syncthreads();
    if (slice == 0 && sB < T) {
        float r = __fadd_rn(__fadd_rn(s_part[0][x], s_part[1][x]),
                            __fadd_rn(s_part[2][x], s_part[3][x]));
        out[sB] = r;
    }
}

extern "C" void kernel_launch(void* const* d_in, const int* in_sizes, int n_in,
                              void* d_out, int out_size)
{
    const float* amp = (const float*)d_in[0];
    const float* tau = (const float*)d_in[1];
    const float* om  = (const float*)d_in[2];
    const float* sg  = (const float*)d_in[3];
    const float* ph  = (const float*)d_in[4];
    const float* gm  = (const float*)d_in[5];
    // d_in[6] = num_samples scalar — T comes from out_size.

    int N = in_sizes[0];
    int T = out_size;
    int num_bins  = (T + BIN - 1) / BIN;          // 72000 -> 141
    if (num_bins > MAX_BINS) num_bins = MAX_BINS;
    int num_tiles = (T + RTILE - 1) / RTILE;      // 72000 -> 282

    bin_kernel<<<num_bins, 512>>>(amp, tau, om, sg, ph, gm, N, num_bins, T);
    render_kernel<<<num_tiles, 512>>>((float*)d_out, T);
}